// round 1
// baseline (speedup 1.0000x reference)
#include <cuda_runtime.h>
#include <stdint.h>

// BloomEmbedding: out[n, h*32 + j] = tables[h, hash(ids[n], 42+h), j]
// ids: [4096*200] int32, tables: [4, 1000000, 32] f32, out: [819200, 128] f32

#define TABLE_SIZE 1000000u
#define NUM_HASH 4
#define SUB_DIM 32
#define EMB_DIM 128
#define SEED 42u

__device__ __forceinline__ uint32_t hash_id(uint32_t id, uint32_t seed) {
    uint32_t x = id + seed;
    x ^= x >> 16;
    x *= 0x7FEB352Du;
    x ^= x >> 15;
    x *= 0x846CA68Bu;
    x ^= x >> 16;
    return x % TABLE_SIZE;
}

__global__ void bloom_embedding_kernel(const int* __restrict__ ids,
                                       const float4* __restrict__ tables,
                                       float4* __restrict__ out,
                                       int n_ids) {
    int t = blockIdx.x * blockDim.x + threadIdx.x;
    int total = n_ids * 32;             // one float4 per thread
    if (t >= total) return;

    int n    = t >> 5;                   // id index
    int lane = t & 31;                   // 0..31 within the 128-float row
    int h    = lane >> 3;                // hash table 0..3
    int j    = lane & 7;                 // float4 within the 32-float sub-row

    uint32_t id  = (uint32_t)__ldg(ids + n);
    uint32_t idx = hash_id(id, SEED + (uint32_t)h);

    // tables laid out as [H][TABLE_SIZE][32 floats] = [H][TABLE_SIZE][8 float4]
    size_t src = ((size_t)h * TABLE_SIZE + idx) * 8u + (size_t)j;
    float4 v = __ldg(tables + src);

    // out row n is 128 floats = 32 float4; lane == h*8 + j
    out[(size_t)n * 32u + (size_t)lane] = v;
}

extern "C" void kernel_launch(void* const* d_in, const int* in_sizes, int n_in,
                              void* d_out, int out_size) {
    const int*    ids    = (const int*)d_in[0];
    const float4* tables = (const float4*)d_in[1];
    float4*       out    = (float4*)d_out;

    int n_ids = in_sizes[0];             // 4096*200 = 819200
    int total = n_ids * 32;
    int threads = 256;
    int blocks = (total + threads - 1) / threads;
    bloom_embedding_kernel<<<blocks, threads>>>(ids, tables, out, n_ids);
}